// round 8
// baseline (speedup 1.0000x reference)
#include <cuda_runtime.h>
#include <cstdint>

#define T_STEPS 2048
#define BATCH   64
#define IDIM    512
#define HDIM    512

#define N_PAIRS 8             // pairs of 4-row groups (8 rows per pair)
#define COLS_PER_BLK 32

typedef unsigned long long u64;

// ---------------- scratch -----------------------------------------------
__device__ float g_xf[(long)T_STEPS * BATCH * HDIM];
__device__ float g_xh[(long)T_STEPS * BATCH * HDIM];
__device__ float g_hbuf[BATCH * HDIM];
__device__ float g_gbuf[BATCH * HDIM];
__device__ unsigned int g_cnt[512];   // per pair: 4 counters 32B apart

// ---------------- packed f32x2 helpers -----------------------------------
__device__ __forceinline__ u64 pack2(float x, float y) {
    u64 r; asm("mov.b64 %0, {%1, %2};" : "=l"(r) : "f"(x), "f"(y)); return r;
}
__device__ __forceinline__ u64 ffma2(u64 a, u64 b, u64 c) {
    u64 d; asm("fma.rn.f32x2 %0, %1, %2, %3;" : "=l"(d) : "l"(a), "l"(b), "l"(c));
    return d;
}
__device__ __forceinline__ float2 unpack2(u64 a) {
    float2 r; asm("mov.b64 {%0, %1}, %2;" : "=f"(r.x), "=f"(r.y) : "l"(a)); return r;
}
__device__ __forceinline__ float4 ldcg4(const float4* p) {
    float4 v;
    asm volatile("ld.global.cg.v4.f32 {%0,%1,%2,%3}, [%4];"
                 : "=f"(v.x), "=f"(v.y), "=f"(v.z), "=f"(v.w) : "l"(p));
    return v;
}
__device__ __forceinline__ void red_release(unsigned int* p) {
    asm volatile("red.release.gpu.global.add.u32 [%0], 1;" :: "l"(p) : "memory");
}
__device__ __forceinline__ unsigned int ld_acq(const unsigned int* p) {
    unsigned int v;
    asm volatile("ld.acquire.gpu.global.u32 %0, [%1];" : "=r"(v) : "l"(p) : "memory");
    return v;
}
__device__ __forceinline__ float sigmoid_f(float x) {
    return __fdividef(1.0f, 1.0f + __expf(-x));
}
__device__ __forceinline__ float tanh_ap(float x) {
    float y; asm("tanh.approx.f32 %0, %1;" : "=f"(y) : "f"(x)); return y;
}

// lane-0 poll + warp broadcast
__device__ __forceinline__ void poll_wait(unsigned int* c, unsigned int tgt, int j) {
    if (j == 0) while (ld_acq(c) < tgt) { }
    __syncwarp();
}
// per-warp gather: 4 rows x 128-float k-slice -> smem rows at stride 128
__device__ __forceinline__ void gather4(float* dst, const float* src, int j) {
    const float4* s = (const float4*)src;
    float4 v0 = ldcg4(s + j);
    float4 v1 = ldcg4(s + 128 + j);
    float4 v2 = ldcg4(s + 256 + j);
    float4 v3 = ldcg4(s + 384 + j);
    *(float4*)&dst[        4 * j] = v0;
    *(float4*)&dst[128 +   4 * j] = v1;
    *(float4*)&dst[256 +   4 * j] = v2;
    *(float4*)&dst[384 +   4 * j] = v3;
}
// GEMM phase, weights in registers (pre-packed u64 pairs)
__device__ __forceinline__ void gemm_reg(const u64* __restrict__ w2,
                                         const float* __restrict__ sb,
                                         float* __restrict__ part, int w, int j)
{
    u64 a0 = 0ull, a1 = 0ull, a2 = 0ull, a3 = 0ull;
    #pragma unroll
    for (int i = 0; i < 32; i++) {
        u64 wlo = w2[2*i], whi = w2[2*i+1];
        float4 x0 = *(const float4*)&sb[        4 * i];
        float4 x1 = *(const float4*)&sb[128 +   4 * i];
        float4 x2 = *(const float4*)&sb[256 +   4 * i];
        float4 x3 = *(const float4*)&sb[384 +   4 * i];
        a0 = ffma2(wlo, pack2(x0.x, x0.y), a0);
        a0 = ffma2(whi, pack2(x0.z, x0.w), a0);
        a1 = ffma2(wlo, pack2(x1.x, x1.y), a1);
        a1 = ffma2(whi, pack2(x1.z, x1.w), a1);
        a2 = ffma2(wlo, pack2(x2.x, x2.y), a2);
        a2 = ffma2(whi, pack2(x2.z, x2.w), a2);
        a3 = ffma2(wlo, pack2(x3.x, x3.y), a3);
        a3 = ffma2(whi, pack2(x3.z, x3.w), a3);
    }
    float2 r0 = unpack2(a0), r1 = unpack2(a1), r2 = unpack2(a2), r3 = unpack2(a3);
    part[(0 * 4 + w) * 32 + j] = r0.x + r0.y;
    part[(1 * 4 + w) * 32 + j] = r1.x + r1.y;
    part[(2 * 4 + w) * 32 + j] = r2.x + r2.y;
    part[(3 * 4 + w) * 32 + j] = r3.x + r3.y;
}
// GEMM phase, weights from SMEM (conflict-free 132-stride private slice)
__device__ __forceinline__ void gemm_smem(const float* __restrict__ wr,
                                          const float* __restrict__ sb,
                                          float* __restrict__ part, int w, int j)
{
    u64 a0 = 0ull, a1 = 0ull, a2 = 0ull, a3 = 0ull;
    #pragma unroll
    for (int i = 0; i < 32; i++) {
        float4 wv = *(const float4*)&wr[4 * i];
        u64 wlo = pack2(wv.x, wv.y), whi = pack2(wv.z, wv.w);
        float4 x0 = *(const float4*)&sb[        4 * i];
        float4 x1 = *(const float4*)&sb[128 +   4 * i];
        float4 x2 = *(const float4*)&sb[256 +   4 * i];
        float4 x3 = *(const float4*)&sb[384 +   4 * i];
        a0 = ffma2(wlo, pack2(x0.x, x0.y), a0);
        a0 = ffma2(whi, pack2(x0.z, x0.w), a0);
        a1 = ffma2(wlo, pack2(x1.x, x1.y), a1);
        a1 = ffma2(whi, pack2(x1.z, x1.w), a1);
        a2 = ffma2(wlo, pack2(x2.x, x2.y), a2);
        a2 = ffma2(whi, pack2(x2.z, x2.w), a2);
        a3 = ffma2(wlo, pack2(x3.x, x3.y), a3);
        a3 = ffma2(whi, pack2(x3.z, x3.w), a3);
    }
    float2 r0 = unpack2(a0), r1 = unpack2(a1), r2 = unpack2(a2), r3 = unpack2(a3);
    part[(0 * 4 + w) * 32 + j] = r0.x + r0.y;
    part[(1 * 4 + w) * 32 + j] = r1.x + r1.y;
    part[(2 * 4 + w) * 32 + j] = r2.x + r2.y;
    part[(3 * 4 + w) * 32 + j] = r3.x + r3.y;
}

// ============================================================================
// Phase 1: input projections. Block (0,0,0) zeroes counters; blocks
// (x<16,0,0) seed g_hbuf from h0.
// ============================================================================
__global__ __launch_bounds__(256) void proj_kernel(
    const float* __restrict__ X,  const float* __restrict__ h0,
    const float* __restrict__ Wf, const float* __restrict__ bf,
    const float* __restrict__ Wh, const float* __restrict__ bh)
{
    if (blockIdx.y == 0 && blockIdx.z == 0) {
        if (blockIdx.x == 0) {
            g_cnt[threadIdx.x] = 0u;
            g_cnt[threadIdx.x + 256] = 0u;
        }
        if (blockIdx.x < 16) {
            const float4* s = (const float4*)&h0[blockIdx.x * 4 * HDIM];
            float4* d = (float4*)&g_hbuf[blockIdx.x * 4 * HDIM];
            d[threadIdx.x]       = s[threadIdx.x];
            d[threadIdx.x + 256] = s[threadIdx.x + 256];
        }
    }

    const float* W  = blockIdx.z ? Wh : Wf;
    const float* bv = blockIdx.z ? bh : bf;
    float* out = blockIdx.z ? g_xh : g_xf;

    __shared__ float As[16][132];
    __shared__ float Bs[16][68];

    const int tid = threadIdx.x;
    const int tx = tid & 15;
    const int ty = tid >> 4;
    const long m0 = (long)blockIdx.x * 128;
    const int  n0 = blockIdx.y * 64;

    u64 acc[4][4];
    #pragma unroll
    for (int p = 0; p < 4; p++)
        #pragma unroll
        for (int c = 0; c < 4; c++) acc[p][c] = 0ull;

    for (int k0 = 0; k0 < IDIM; k0 += 16) {
        #pragma unroll
        for (int q0 = 0; q0 < 2; q0++) {
            int q = tid + q0 * 256;
            int row = q >> 2;
            int kc  = (q & 3) * 4;
            float4 v = *(const float4*)&X[(m0 + row) * IDIM + k0 + kc];
            As[kc+0][row] = v.x; As[kc+1][row] = v.y;
            As[kc+2][row] = v.z; As[kc+3][row] = v.w;
        }
        {
            int row = tid >> 2;
            int kc  = (tid & 3) * 4;
            float4 v = *(const float4*)&W[(n0 + row) * IDIM + k0 + kc];
            Bs[kc+0][row] = v.x; Bs[kc+1][row] = v.y;
            Bs[kc+2][row] = v.z; Bs[kc+3][row] = v.w;
        }
        __syncthreads();

        #pragma unroll
        for (int kk = 0; kk < 16; kk++) {
            float4 a0 = *(const float4*)&As[kk][ty * 8];
            float4 a1 = *(const float4*)&As[kk][ty * 8 + 4];
            float4 b4 = *(const float4*)&Bs[kk][tx * 4];
            u64 a2[4] = { pack2(a0.x, a0.y), pack2(a0.z, a0.w),
                          pack2(a1.x, a1.y), pack2(a1.z, a1.w) };
            u64 bb[4] = { pack2(b4.x, b4.x), pack2(b4.y, b4.y),
                          pack2(b4.z, b4.z), pack2(b4.w, b4.w) };
            #pragma unroll
            for (int p = 0; p < 4; p++)
                #pragma unroll
                for (int c = 0; c < 4; c++)
                    acc[p][c] = ffma2(a2[p], bb[c], acc[p][c]);
        }
        __syncthreads();
    }

    float4 bias4 = *(const float4*)&bv[n0 + tx * 4];
    #pragma unroll
    for (int p = 0; p < 4; p++) {
        float2 c0 = unpack2(acc[p][0]);
        float2 c1 = unpack2(acc[p][1]);
        float2 c2 = unpack2(acc[p][2]);
        float2 c3 = unpack2(acc[p][3]);
        long mlo = m0 + ty * 8 + 2 * p;
        float4 lo = make_float4(c0.x + bias4.x, c1.x + bias4.y,
                                c2.x + bias4.z, c3.x + bias4.w);
        float4 hi = make_float4(c0.y + bias4.x, c1.y + bias4.y,
                                c2.y + bias4.z, c3.y + bias4.w);
        *(float4*)&out[mlo * HDIM + n0 + tx * 4]       = lo;
        *(float4*)&out[(mlo + 1) * HDIM + n0 + tx * 4] = hi;
    }
}

// ============================================================================
// Phase 2: persistent scan, dual-group software interleave.
// 128 blocks x 128 threads (1/SM). Block serves pair p = blockIdx>>4
// (chain X = rows p*8..p*8+3, chain Y = rows p*8+4..p*8+7) on columns
// j0..j0+31. Weights shared across chains (Wf regs, Wh smem). Schedule
// A(X) A(Y) B(X) B(Y): every release->wait gap contains a GEMM phase.
// ============================================================================
#define WH_STRIDE 132
#define SCAN_SMEM ((128 * WH_STRIDE + 2 * 4 * 512 + 4 * 512) * 4)

__global__ void __launch_bounds__(128, 1) scan_kernel(
    const float* __restrict__ h0,
    const float* __restrict__ Whf,
    const float* __restrict__ Whh,
    float* __restrict__ out)
{
    extern __shared__ float smem[];
    float* whs = smem;                       // 128 x 132
    float* sbX = whs + 128 * WH_STRIDE;      // 4 warps x 512
    float* sbY = sbX + 4 * 512;
    float* pAX = sbY + 4 * 512;              // 512 each
    float* pAY = pAX + 512;
    float* pBX = pAY + 512;
    float* pBY = pBX + 512;

    const int tid  = threadIdx.x;
    const int j    = tid & 31;
    const int w    = tid >> 5;
    const int pair = blockIdx.x >> 4;
    const int j0   = (blockIdx.x & 15) * COLS_PER_BLK;
    const int b0X  = pair * 8;
    const int b0Y  = b0X + 4;
    const int kb   = w * 128;

    // Wf slice -> registers (shared by both chains)
    u64 wf2[64];
    #pragma unroll
    for (int i = 0; i < 32; i++) {
        float4 v = *(const float4*)&Whf[(j0 + j) * HDIM + kb + 4 * i];
        wf2[2*i] = pack2(v.x, v.y); wf2[2*i+1] = pack2(v.z, v.w);
    }
    // Wh slice -> private SMEM region
    float* wr = &whs[(w * 32 + j) * WH_STRIDE];
    #pragma unroll
    for (int i = 0; i < 32; i++)
        *(float4*)&wr[4 * i] = *(const float4*)&Whh[(j0 + j) * HDIM + kb + 4 * i];

    float hpX = h0[(b0X + w) * HDIM + j0 + j];
    float hpY = h0[(b0Y + w) * HDIM + j0 + j];
    __syncthreads();

    unsigned int* cAX = &g_cnt[pair * 32 + 0];
    unsigned int* cBX = &g_cnt[pair * 32 + 8];
    unsigned int* cAY = &g_cnt[pair * 32 + 16];
    unsigned int* cBY = &g_cnt[pair * 32 + 24];

    float* sbXw = &sbX[w * 512];
    float* sbYw = &sbY[w * 512];
    const long xstep = (long)BATCH * HDIM;
    long xoffX = (long)(b0X + w) * HDIM + j0 + j;
    long xoffY = (long)(b0Y + w) * HDIM + j0 + j;

    float fX = 0.0f, fY = 0.0f;

    for (int t = 0; t < T_STEPS; t++) {
        const unsigned int tgt = (unsigned int)(t + 1) * 64u;
        const float xfX = __ldcs(&g_xf[xoffX]);
        const float xhX = __ldcs(&g_xh[xoffX]);
        const float xfY = __ldcs(&g_xf[xoffY]);
        const float xhY = __ldcs(&g_xh[xoffY]);

        // ---- 1-3: A(X) ----
        if (t > 0) poll_wait(cBX, tgt - 64u, j);
        gather4(sbXw, &g_hbuf[b0X * HDIM + kb], j);
        __syncwarp();
        gemm_reg(wf2, sbXw, pAX, w, j);
        __syncthreads();
        {
            float s = xfX;
            #pragma unroll
            for (int q = 0; q < 4; q++) s += pAX[(w * 4 + q) * 32 + j];
            fX = sigmoid_f(s);
            g_gbuf[(b0X + w) * HDIM + j0 + j] = fX * hpX;
        }
        __syncwarp();
        if (j == 0) red_release(cAX);

        // ---- 4-6: A(Y) ----
        if (t > 0) poll_wait(cBY, tgt - 64u, j);
        gather4(sbYw, &g_hbuf[b0Y * HDIM + kb], j);
        __syncwarp();
        gemm_reg(wf2, sbYw, pAY, w, j);
        __syncthreads();
        {
            float s = xfY;
            #pragma unroll
            for (int q = 0; q < 4; q++) s += pAY[(w * 4 + q) * 32 + j];
            fY = sigmoid_f(s);
            g_gbuf[(b0Y + w) * HDIM + j0 + j] = fY * hpY;
        }
        __syncwarp();
        if (j == 0) red_release(cAY);

        // ---- 7-9: B(X) ----
        poll_wait(cAX, tgt, j);
        gather4(sbXw, &g_gbuf[b0X * HDIM + kb], j);
        __syncwarp();
        gemm_smem(wr, sbXw, pBX, w, j);
        __syncthreads();
        {
            float s = xhX;
            #pragma unroll
            for (int q = 0; q < 4; q++) s += pBX[(w * 4 + q) * 32 + j];
            float ht = tanh_ap(s);
            float hn = fmaf(fX, ht - hpX, hpX);
            __stcs(&out[xoffX], hn);
            g_hbuf[(b0X + w) * HDIM + j0 + j] = hn;
            if (t == T_STEPS - 1)
                out[(long)T_STEPS * xstep + (b0X + w) * HDIM + j0 + j] = hn;
            hpX = hn;
        }
        __syncwarp();
        if (j == 0) red_release(cBX);

        // ---- 10-12: B(Y) ----
        poll_wait(cAY, tgt, j);
        gather4(sbYw, &g_gbuf[b0Y * HDIM + kb], j);
        __syncwarp();
        gemm_smem(wr, sbYw, pBY, w, j);
        __syncthreads();
        {
            float s = xhY;
            #pragma unroll
            for (int q = 0; q < 4; q++) s += pBY[(w * 4 + q) * 32 + j];
            float ht = tanh_ap(s);
            float hn = fmaf(fY, ht - hpY, hpY);
            __stcs(&out[xoffY], hn);
            g_hbuf[(b0Y + w) * HDIM + j0 + j] = hn;
            if (t == T_STEPS - 1)
                out[(long)T_STEPS * xstep + (b0Y + w) * HDIM + j0 + j] = hn;
            hpY = hn;
        }
        __syncwarp();
        if (j == 0) red_release(cBY);

        xoffX += xstep;
        xoffY += xstep;
    }
}

// ============================================================================
extern "C" void kernel_launch(void* const* d_in, const int* in_sizes, int n_in,
                              void* d_out, int out_size)
{
    const float* x   = (const float*)d_in[0];
    const float* h0  = (const float*)d_in[1];
    const float* Wxf = (const float*)d_in[2];
    const float* Whf = (const float*)d_in[3];
    const float* bf  = (const float*)d_in[4];
    const float* Wxh = (const float*)d_in[5];
    const float* Whh = (const float*)d_in[6];
    const float* bh  = (const float*)d_in[7];
    float* out = (float*)d_out;

    cudaFuncSetAttribute(scan_kernel,
                         cudaFuncAttributeMaxDynamicSharedMemorySize, SCAN_SMEM);

    dim3 pgrid((T_STEPS * BATCH) / 128, HDIM / 64, 2);
    proj_kernel<<<pgrid, 256>>>(x, h0, Wxf, bf, Wxh, bh);

    scan_kernel<<<N_PAIRS * 16, 128, SCAN_SMEM>>>(h0, Whf, Whh, out);
}

// round 9
// speedup vs baseline: 1.1775x; 1.1775x over previous
#include <cuda_runtime.h>
#include <cstdint>

#define T_STEPS 2048
#define BATCH   64
#define IDIM    512
#define HDIM    512

#define N_CHAINS 16           // 16 chains of 4 batch rows
#define COLS_PER_BLK 32

typedef unsigned long long u64;

// ---------------- scratch -----------------------------------------------
__device__ float g_xf[(long)T_STEPS * BATCH * HDIM];
__device__ float g_xh[(long)T_STEPS * BATCH * HDIM];
__device__ float g_hbuf[BATCH * HDIM];
__device__ float g_gbuf[BATCH * HDIM];
__device__ unsigned int g_cnt[512];   // chain c: cA at c*16, cB at c*16+8

// ---------------- packed f32x2 helpers -----------------------------------
__device__ __forceinline__ u64 pack2(float x, float y) {
    u64 r; asm("mov.b64 %0, {%1, %2};" : "=l"(r) : "f"(x), "f"(y)); return r;
}
__device__ __forceinline__ u64 ffma2(u64 a, u64 b, u64 c) {
    u64 d; asm("fma.rn.f32x2 %0, %1, %2, %3;" : "=l"(d) : "l"(a), "l"(b), "l"(c));
    return d;
}
__device__ __forceinline__ float2 unpack2(u64 a) {
    float2 r; asm("mov.b64 {%0, %1}, %2;" : "=f"(r.x), "=f"(r.y) : "l"(a)); return r;
}
__device__ __forceinline__ float4 ldcg4(const float4* p) {
    float4 v;
    asm volatile("ld.global.cg.v4.f32 {%0,%1,%2,%3}, [%4];"
                 : "=f"(v.x), "=f"(v.y), "=f"(v.z), "=f"(v.w) : "l"(p));
    return v;
}
__device__ __forceinline__ void red_release(unsigned int* p) {
    asm volatile("red.release.gpu.global.add.u32 [%0], 1;" :: "l"(p) : "memory");
}
__device__ __forceinline__ unsigned int ld_acq(const unsigned int* p) {
    unsigned int v;
    asm volatile("ld.acquire.gpu.global.u32 %0, [%1];" : "=r"(v) : "l"(p) : "memory");
    return v;
}
__device__ __forceinline__ float sigmoid_f(float x) {
    return __fdividef(1.0f, 1.0f + __expf(-x));
}
__device__ __forceinline__ float tanh_ap(float x) {
    float y; asm("tanh.approx.f32 %0, %1;" : "=f"(y) : "f"(x)); return y;
}
// named barrier for a 128-thread sub-block (IDs 1 and 2; 0 = syncthreads)
__device__ __forceinline__ void bar_sub(int id) {
    asm volatile("bar.sync %0, 128;" :: "r"(id) : "memory");
}
// lane-0 poll + warp broadcast (syncwarp carries the ordering to all lanes)
__device__ __forceinline__ void poll_wait(unsigned int* c, unsigned int tgt, int j) {
    if (j == 0) while (ld_acq(c) < tgt) { }
    __syncwarp();
}

// ============================================================================
// Phase 1: input projections (unchanged). Block (0,0,0) zeroes counters;
// blocks (x<16,0,0) seed g_hbuf from h0.
// ============================================================================
__global__ __launch_bounds__(256) void proj_kernel(
    const float* __restrict__ X,  const float* __restrict__ h0,
    const float* __restrict__ Wf, const float* __restrict__ bf,
    const float* __restrict__ Wh, const float* __restrict__ bh)
{
    if (blockIdx.y == 0 && blockIdx.z == 0) {
        if (blockIdx.x == 0) {
            g_cnt[threadIdx.x] = 0u;
            g_cnt[threadIdx.x + 256] = 0u;
        }
        if (blockIdx.x < 16) {
            const float4* s = (const float4*)&h0[blockIdx.x * 4 * HDIM];
            float4* d = (float4*)&g_hbuf[blockIdx.x * 4 * HDIM];
            d[threadIdx.x]       = s[threadIdx.x];
            d[threadIdx.x + 256] = s[threadIdx.x + 256];
        }
    }

    const float* W  = blockIdx.z ? Wh : Wf;
    const float* bv = blockIdx.z ? bh : bf;
    float* out = blockIdx.z ? g_xh : g_xf;

    __shared__ float As[16][132];
    __shared__ float Bs[16][68];

    const int tid = threadIdx.x;
    const int tx = tid & 15;
    const int ty = tid >> 4;
    const long m0 = (long)blockIdx.x * 128;
    const int  n0 = blockIdx.y * 64;

    u64 acc[4][4];
    #pragma unroll
    for (int p = 0; p < 4; p++)
        #pragma unroll
        for (int c = 0; c < 4; c++) acc[p][c] = 0ull;

    for (int k0 = 0; k0 < IDIM; k0 += 16) {
        #pragma unroll
        for (int q0 = 0; q0 < 2; q0++) {
            int q = tid + q0 * 256;
            int row = q >> 2;
            int kc  = (q & 3) * 4;
            float4 v = *(const float4*)&X[(m0 + row) * IDIM + k0 + kc];
            As[kc+0][row] = v.x; As[kc+1][row] = v.y;
            As[kc+2][row] = v.z; As[kc+3][row] = v.w;
        }
        {
            int row = tid >> 2;
            int kc  = (tid & 3) * 4;
            float4 v = *(const float4*)&W[(n0 + row) * IDIM + k0 + kc];
            Bs[kc+0][row] = v.x; Bs[kc+1][row] = v.y;
            Bs[kc+2][row] = v.z; Bs[kc+3][row] = v.w;
        }
        __syncthreads();

        #pragma unroll
        for (int kk = 0; kk < 16; kk++) {
            float4 a0 = *(const float4*)&As[kk][ty * 8];
            float4 a1 = *(const float4*)&As[kk][ty * 8 + 4];
            float4 b4 = *(const float4*)&Bs[kk][tx * 4];
            u64 a2[4] = { pack2(a0.x, a0.y), pack2(a0.z, a0.w),
                          pack2(a1.x, a1.y), pack2(a1.z, a1.w) };
            u64 bb[4] = { pack2(b4.x, b4.x), pack2(b4.y, b4.y),
                          pack2(b4.z, b4.z), pack2(b4.w, b4.w) };
            #pragma unroll
            for (int p = 0; p < 4; p++)
                #pragma unroll
                for (int c = 0; c < 4; c++)
                    acc[p][c] = ffma2(a2[p], bb[c], acc[p][c]);
        }
        __syncthreads();
    }

    float4 bias4 = *(const float4*)&bv[n0 + tx * 4];
    #pragma unroll
    for (int p = 0; p < 4; p++) {
        float2 c0 = unpack2(acc[p][0]);
        float2 c1 = unpack2(acc[p][1]);
        float2 c2 = unpack2(acc[p][2]);
        float2 c3 = unpack2(acc[p][3]);
        long mlo = m0 + ty * 8 + 2 * p;
        float4 lo = make_float4(c0.x + bias4.x, c1.x + bias4.y,
                                c2.x + bias4.z, c3.x + bias4.w);
        float4 hi = make_float4(c0.y + bias4.x, c1.y + bias4.y,
                                c2.y + bias4.z, c3.y + bias4.w);
        *(float4*)&out[mlo * HDIM + n0 + tx * 4]       = lo;
        *(float4*)&out[(mlo + 1) * HDIM + n0 + tx * 4] = hi;
    }
}

// ============================================================================
// Phase 2: persistent scan, barrier-decoupled dual chains.
// 128 blocks x 256 threads (1/SM). Block = 2 independent 128-thread
// sub-blocks handling chains 2p and 2p+1 (p = blockIdx>>4) on the same
// 32-column set (weights shared in SMEM). Sub-blocks sync only via named
// barriers (1 and 2); never via __syncthreads after init. Warp w of a
// sub-block owns k-slice [w*128, w*128+128) and finalize row w.
// ============================================================================
#define WPAD 516
#define SCAN_SMEM ((2 * 32 * WPAD + 2 * 4 * 512 + 2 * 512) * 4)

__global__ void __launch_bounds__(256, 1) scan_kernel(
    const float* __restrict__ h0,
    const float* __restrict__ Whf,
    const float* __restrict__ Whh,
    float* __restrict__ out)
{
    extern __shared__ float smem[];
    float* Wf_s = smem;                      // 32 x 516
    float* Wh_s = Wf_s + 32 * WPAD;          // 32 x 516
    float* srcA = Wh_s + 32 * WPAD;          // sub 0: 4 rows x 512
    float* srcB = srcA + 4 * 512;            // sub 1
    float* prtA = srcB + 4 * 512;            // sub 0: [r*4+ks]*32+j
    float* prtB = prtA + 512;                // sub 1

    const int tid  = threadIdx.x;
    const int sub  = tid >> 7;               // 0 or 1
    const int stid = tid & 127;
    const int w    = stid >> 5;              // warp in sub-block: k-slice + row
    const int j    = stid & 31;
    const int col  = blockIdx.x & 15;
    const int j0   = col * COLS_PER_BLK;
    const int chain = (blockIdx.x >> 4) * 2 + sub;
    const int b0   = chain * 4;
    const int kb   = w * 128;
    const int barid = 1 + sub;

    // cooperative weight load (shared by both sub-blocks)
    for (int i = tid; i < 32 * 128; i += 256) {
        int r = i >> 7, c4 = (i & 127) * 4;
        *(float4*)&Wf_s[r * WPAD + c4] = *(const float4*)&Whf[(j0 + r) * HDIM + c4];
        *(float4*)&Wh_s[r * WPAD + c4] = *(const float4*)&Whh[(j0 + r) * HDIM + c4];
    }
    __syncthreads();    // the ONLY block-wide sync

    float* src = sub ? srcB : srcA;
    float* prt = sub ? prtB : prtA;
    float* sw  = src + kb;                   // this warp's k-window base

    unsigned int* cA = &g_cnt[chain * 16 + 0];
    unsigned int* cB = &g_cnt[chain * 16 + 8];

    const float* wfr = &Wf_s[j * WPAD + kb];
    const float* whr = &Wh_s[j * WPAD + kb];

    float hp = h0[(b0 + w) * HDIM + j0 + j];
    float f_reg = 0.0f;

    const long xstep = (long)BATCH * HDIM;
    long xoff = (long)(b0 + w) * HDIM + j0 + j;

    for (int t = 0; t < T_STEPS; t++) {
        const unsigned int tgt = (unsigned int)(t + 1) * 64u;
        const float xf_v = __ldcs(&g_xf[xoff]);
        const float xh_v = __ldcs(&g_xh[xoff]);

        // ---- wait for h_{t-1}, gather own k-window (warp-private) ----
        if (t > 0) poll_wait(cB, tgt - 64u, j);
        {
            const float4* hb = (const float4*)&g_hbuf[b0 * HDIM + kb];
            float4 v0 = ldcg4(hb + j);
            float4 v1 = ldcg4(hb + 128 + j);
            float4 v2 = ldcg4(hb + 256 + j);
            float4 v3 = ldcg4(hb + 384 + j);
            *(float4*)&sw[        4 * j] = v0;
            *(float4*)&sw[512 +   4 * j] = v1;   // row stride 512
            *(float4*)&sw[1024 +  4 * j] = v2;
            *(float4*)&sw[1536 +  4 * j] = v3;
        }
        __syncwarp();

        // ---- GEMM A (f gate): 4 rows x 128 k, Wf from SMEM ----
        {
            u64 a0 = 0ull, a1 = 0ull, a2 = 0ull, a3 = 0ull;
            #pragma unroll
            for (int i = 0; i < 32; i++) {
                float4 wv = *(const float4*)&wfr[4 * i];
                u64 wlo = pack2(wv.x, wv.y), whi = pack2(wv.z, wv.w);
                float4 x0 = *(const float4*)&sw[        4 * i];
                float4 x1 = *(const float4*)&sw[512 +   4 * i];
                float4 x2 = *(const float4*)&sw[1024 +  4 * i];
                float4 x3 = *(const float4*)&sw[1536 +  4 * i];
                a0 = ffma2(wlo, pack2(x0.x, x0.y), a0);
                a0 = ffma2(whi, pack2(x0.z, x0.w), a0);
                a1 = ffma2(wlo, pack2(x1.x, x1.y), a1);
                a1 = ffma2(whi, pack2(x1.z, x1.w), a1);
                a2 = ffma2(wlo, pack2(x2.x, x2.y), a2);
                a2 = ffma2(whi, pack2(x2.z, x2.w), a2);
                a3 = ffma2(wlo, pack2(x3.x, x3.y), a3);
                a3 = ffma2(whi, pack2(x3.z, x3.w), a3);
            }
            float2 r0 = unpack2(a0), r1 = unpack2(a1);
            float2 r2 = unpack2(a2), r3 = unpack2(a3);
            prt[(0 * 4 + w) * 32 + j] = r0.x + r0.y;
            prt[(1 * 4 + w) * 32 + j] = r1.x + r1.y;
            prt[(2 * 4 + w) * 32 + j] = r2.x + r2.y;
            prt[(3 * 4 + w) * 32 + j] = r3.x + r3.y;
        }
        bar_sub(barid);

        // ---- finalize A: warp w owns row w; publish g; release cA ----
        {
            float s = xf_v;
            #pragma unroll
            for (int q = 0; q < 4; q++) s += prt[(w * 4 + q) * 32 + j];
            f_reg = sigmoid_f(s);
            g_gbuf[(b0 + w) * HDIM + j0 + j] = f_reg * hp;
        }
        __syncwarp();
        if (j == 0) red_release(cA);

        // ---- wait for g_t, gather own k-window ----
        poll_wait(cA, tgt, j);
        {
            const float4* gb = (const float4*)&g_gbuf[b0 * HDIM + kb];
            float4 v0 = ldcg4(gb + j);
            float4 v1 = ldcg4(gb + 128 + j);
            float4 v2 = ldcg4(gb + 256 + j);
            float4 v3 = ldcg4(gb + 384 + j);
            *(float4*)&sw[        4 * j] = v0;
            *(float4*)&sw[512 +   4 * j] = v1;
            *(float4*)&sw[1024 +  4 * j] = v2;
            *(float4*)&sw[1536 +  4 * j] = v3;
        }
        __syncwarp();

        // ---- GEMM B (candidate): Wh from SMEM ----
        {
            u64 a0 = 0ull, a1 = 0ull, a2 = 0ull, a3 = 0ull;
            #pragma unroll
            for (int i = 0; i < 32; i++) {
                float4 wv = *(const float4*)&whr[4 * i];
                u64 wlo = pack2(wv.x, wv.y), whi = pack2(wv.z, wv.w);
                float4 x0 = *(const float4*)&sw[        4 * i];
                float4 x1 = *(const float4*)&sw[512 +   4 * i];
                float4 x2 = *(const float4*)&sw[1024 +  4 * i];
                float4 x3 = *(const float4*)&sw[1536 +  4 * i];
                a0 = ffma2(wlo, pack2(x0.x, x0.y), a0);
                a0 = ffma2(whi, pack2(x0.z, x0.w), a0);
                a1 = ffma2(wlo, pack2(x1.x, x1.y), a1);
                a1 = ffma2(whi, pack2(x1.z, x1.w), a1);
                a2 = ffma2(wlo, pack2(x2.x, x2.y), a2);
                a2 = ffma2(whi, pack2(x2.z, x2.w), a2);
                a3 = ffma2(wlo, pack2(x3.x, x3.y), a3);
                a3 = ffma2(whi, pack2(x3.z, x3.w), a3);
            }
            float2 r0 = unpack2(a0), r1 = unpack2(a1);
            float2 r2 = unpack2(a2), r3 = unpack2(a3);
            prt[(0 * 4 + w) * 32 + j] = r0.x + r0.y;
            prt[(1 * 4 + w) * 32 + j] = r1.x + r1.y;
            prt[(2 * 4 + w) * 32 + j] = r2.x + r2.y;
            prt[(3 * 4 + w) * 32 + j] = r3.x + r3.y;
        }
        bar_sub(barid);

        // ---- finalize B: blend, emit y/h; release cB ----
        {
            float s = xh_v;
            #pragma unroll
            for (int q = 0; q < 4; q++) s += prt[(w * 4 + q) * 32 + j];
            float ht = tanh_ap(s);
            float hn = fmaf(f_reg, ht - hp, hp);
            __stcs(&out[xoff], hn);
            g_hbuf[(b0 + w) * HDIM + j0 + j] = hn;
            if (t == T_STEPS - 1)
                out[(long)T_STEPS * xstep + (b0 + w) * HDIM + j0 + j] = hn;
            hp = hn;
        }
        __syncwarp();
        if (j == 0) red_release(cB);

        xoff += xstep;
    }
}

// ============================================================================
extern "C" void kernel_launch(void* const* d_in, const int* in_sizes, int n_in,
                              void* d_out, int out_size)
{
    const float* x   = (const float*)d_in[0];
    const float* h0  = (const float*)d_in[1];
    const float* Wxf = (const float*)d_in[2];
    const float* Whf = (const float*)d_in[3];
    const float* bf  = (const float*)d_in[4];
    const float* Wxh = (const float*)d_in[5];
    const float* Whh = (const float*)d_in[6];
    const float* bh  = (const float*)d_in[7];
    float* out = (float*)d_out;

    cudaFuncSetAttribute(scan_kernel,
                         cudaFuncAttributeMaxDynamicSharedMemorySize, SCAN_SMEM);

    dim3 pgrid((T_STEPS * BATCH) / 128, HDIM / 64, 2);
    proj_kernel<<<pgrid, 256>>>(x, h0, Wxf, bf, Wxh, bh);

    scan_kernel<<<128, 256, SCAN_SMEM>>>(h0, Whf, Whh, out);
}